// round 5
// baseline (speedup 1.0000x reference)
#include <cuda_runtime.h>
#include <cuda_bf16.h>
#include <cstdint>

#define NVEC    131072
#define DDIM    128
#define KCODES  1024
#define BM      128              // vectors per CTA
#define CHUNK   64               // codes per chunk
#define NCHUNKS (KCODES / CHUNK)
#define NTHREADS 256
#define ASTR    136              // bf16 row stride (272 B) -> conflict-free frags
#define WSTR    (ASTR / 2)       // 68 words
#define MARGIN  3e-3f
#define TCAND   8                // candidate slots per (vector, lane-group)

#define SM_A 0
#define SM_B (BM * ASTR * 2)                 // 34816
#define SM_S (SM_B + CHUNK * ASTR * 2)       // 52224
#define SMEM_TOTAL (SM_S + KCODES * 4)       // 56320

__device__ unsigned g_cbw[KCODES * 64];      // codebook as bf16x2 words
__device__ float    g_snorm[KCODES];
__device__ int      g_cand[NVEC * 4 * TCAND];
__device__ int      g_ccnt[NVEC * 4];
__device__ int      g_idx[NVEC];

__device__ __forceinline__ void mma16816(float* c, const unsigned* a,
                                         unsigned b0, unsigned b1) {
    asm volatile(
        "mma.sync.aligned.m16n8k16.row.col.f32.bf16.bf16.f32 "
        "{%0,%1,%2,%3}, {%4,%5,%6,%7}, {%8,%9}, {%0,%1,%2,%3};"
        : "+f"(c[0]), "+f"(c[1]), "+f"(c[2]), "+f"(c[3])
        : "r"(a[0]), "r"(a[1]), "r"(a[2]), "r"(a[3]), "r"(b0), "r"(b1));
}

// Codebook prologue: exact sequential fp32 ||c||^2 + bf16 conversion.
__global__ void cbprep_kernel(const float* __restrict__ cb) {
    int k = blockIdx.x * blockDim.x + threadIdx.x;
    if (k >= KCODES) return;
    const float4* row = (const float4*)(cb + k * DDIM);
    unsigned* dst = g_cbw + k * 64;
    float s = 0.f;
#pragma unroll
    for (int i = 0; i < 32; i++) {
        float4 v = row[i];
        s = __fadd_rn(s, __fmul_rn(v.x, v.x));
        s = __fadd_rn(s, __fmul_rn(v.y, v.y));
        s = __fadd_rn(s, __fmul_rn(v.z, v.z));
        s = __fadd_rn(s, __fmul_rn(v.w, v.w));
        unsigned p0, p1;
        asm("cvt.rn.bf16x2.f32 %0, %1, %2;" : "=r"(p0) : "f"(v.y), "f"(v.x));
        asm("cvt.rn.bf16x2.f32 %0, %1, %2;" : "=r"(p1) : "f"(v.w), "f"(v.z));
        dst[2 * i]     = p0;
        dst[2 * i + 1] = p1;
    }
    g_snorm[k] = s;
}

// Filter: bf16 mma.sync GEMM over all codes; margin-based candidate capture.
// dist' = s_k - 2*p_hat (the per-row ||z||^2 cancels in argmin).
__global__ void __launch_bounds__(NTHREADS, 2)
filter_kernel(const float* __restrict__ z) {
    extern __shared__ char smem[];
    __nv_bfloat16* As  = (__nv_bfloat16*)(smem + SM_A);
    unsigned*      Bs  = (unsigned*)(smem + SM_B);
    float*         ss  = (float*)(smem + SM_S);

    const int tid = threadIdx.x, wid = tid >> 5, lane = tid & 31;
    const int r = lane >> 2, q = lane & 3;
    const int nbase = blockIdx.x * BM;
    const float* zb = z + (size_t)(nbase >> 12) * (DDIM * 4096) + (nbase & 4095);

    for (int i = tid; i < KCODES; i += NTHREADS) ss[i] = g_snorm[i];

    // A fill: gmem [d][v] coalesced -> smem [v][d] bf16.
    for (int e = tid; e < DDIM * BM; e += NTHREADS) {
        int d = e >> 7, i = e & 127;
        As[i * ASTR + d] = __float2bfloat16(zb[(size_t)d * 4096 + i]);
    }
    __syncthreads();

    // Hoist A fragments for all 8 k-steps (invariant across chunks).
    unsigned af[32];
    {
        const __nv_bfloat16* base = As + (wid * 16 + r) * ASTR + q * 2;
#pragma unroll
        for (int ks = 0; ks < 8; ks++) {
            const __nv_bfloat16* p = base + ks * 16;
            af[ks * 4 + 0] = *(const unsigned*)(p);
            af[ks * 4 + 1] = *(const unsigned*)(p + 8 * ASTR);
            af[ks * 4 + 2] = *(const unsigned*)(p + 8);
            af[ks * 4 + 3] = *(const unsigned*)(p + 8 * ASTR + 8);
        }
    }

    float rm0 = 3.4e38f, rm1 = 3.4e38f;
    int cnt0 = 0, cnt1 = 0;
    const int n0 = nbase + wid * 16 + r, n1 = n0 + 8;
    int* cseg0 = g_cand + (n0 * 4 + q) * TCAND;
    int* cseg1 = g_cand + (n1 * 4 + q) * TCAND;

    for (int ch = 0; ch < NCHUNKS; ch++) {
        __syncthreads();
        // B fill: 64 codes x 128 d bf16, uint4 copies, conflict-free.
        {
            const uint4* src = (const uint4*)(g_cbw + ch * CHUNK * 64);
            for (int e = tid; e < CHUNK * 16; e += NTHREADS) {
                int code = e >> 4, w4 = e & 15;
                *(uint4*)(Bs + code * WSTR + w4 * 4) = src[e];
            }
        }
        __syncthreads();

        float acc[32];
#pragma unroll
        for (int t = 0; t < 8; t++) {
            float* c = acc + t * 4;
            c[0] = c[1] = c[2] = c[3] = 0.f;
            const unsigned boff = (unsigned)((t * 8 + r) * WSTR + q);
#pragma unroll
            for (int ks = 0; ks < 8; ks++) {
                unsigned b0 = Bs[boff + ks * 8];
                unsigned b1 = Bs[boff + ks * 8 + 4];
                mma16816(c, af + ks * 4, b0, b1);
            }
        }

        // Epilogue: dist' = s - 2p (overwrite acc), chunk-min first, then push.
        const int kb = ch * CHUNK;
        float cm0 = 3.4e38f, cm1 = 3.4e38f;
#pragma unroll
        for (int t = 0; t < 8; t++) {
            int k = kb + t * 8 + q * 2;
            float s0 = ss[k], s1 = ss[k + 1];
            float d0 = __fmaf_rn(-2.f, acc[t * 4 + 0], s0);
            float d1 = __fmaf_rn(-2.f, acc[t * 4 + 1], s1);
            float d2 = __fmaf_rn(-2.f, acc[t * 4 + 2], s0);
            float d3 = __fmaf_rn(-2.f, acc[t * 4 + 3], s1);
            acc[t * 4 + 0] = d0; acc[t * 4 + 1] = d1;
            acc[t * 4 + 2] = d2; acc[t * 4 + 3] = d3;
            cm0 = fminf(cm0, fminf(d0, d1));
            cm1 = fminf(cm1, fminf(d2, d3));
        }
        rm0 = fminf(rm0, cm0);
        rm1 = fminf(rm1, cm1);
        const float t0 = rm0 + MARGIN, t1 = rm1 + MARGIN;
#pragma unroll
        for (int t = 0; t < 8; t++) {
            int k = kb + t * 8 + q * 2;
            if (acc[t * 4 + 0] <= t0) { if (cnt0 < TCAND) cseg0[cnt0] = k;     cnt0++; }
            if (acc[t * 4 + 1] <= t0) { if (cnt0 < TCAND) cseg0[cnt0] = k + 1; cnt0++; }
            if (acc[t * 4 + 2] <= t1) { if (cnt1 < TCAND) cseg1[cnt1] = k;     cnt1++; }
            if (acc[t * 4 + 3] <= t1) { if (cnt1 < TCAND) cseg1[cnt1] = k + 1; cnt1++; }
        }
        // Sync row-min across the 4 lanes sharing each row (q bits).
        rm0 = fminf(rm0, __shfl_xor_sync(~0u, rm0, 1));
        rm0 = fminf(rm0, __shfl_xor_sync(~0u, rm0, 2));
        rm1 = fminf(rm1, __shfl_xor_sync(~0u, rm1, 1));
        rm1 = fminf(rm1, __shfl_xor_sync(~0u, rm1, 2));
    }

    g_ccnt[n0 * 4 + q] = cnt0;
    g_ccnt[n1 * 4 + q] = cnt1;
}

// Exact rescue: bit-identical round-1 arithmetic on the candidate set.
__global__ void rescue_kernel(const float* __restrict__ z,
                              const float* __restrict__ cb) {
    int n = blockIdx.x * blockDim.x + threadIdx.x;
    int c0 = g_ccnt[n * 4 + 0], c1 = g_ccnt[n * 4 + 1];
    int c2 = g_ccnt[n * 4 + 2], c3 = g_ccnt[n * 4 + 3];
    bool full = (c0 > TCAND) | (c1 > TCAND) | (c2 > TCAND) | (c3 > TCAND);

    float zr[DDIM];
    const float* zp = z + (size_t)(n >> 12) * (DDIM * 4096) + (n & 4095);
#pragma unroll
    for (int d = 0; d < DDIM; d++) zr[d] = zp[(size_t)d * 4096];

    // Exact sequential r (order d = 0..127, separate mul+add as in reference).
    float rr = 0.f;
#pragma unroll
    for (int d = 0; d < DDIM; d++)
        rr = __fadd_rn(rr, __fmul_rn(zr[d], zr[d]));

    float bd = 3.4e38f;
    int bk = 0x7fffffff;

    if (full) {
        for (int k = 0; k < KCODES; k++) {
            const float* crow = cb + k * DDIM;
            float p = 0.f;
#pragma unroll
            for (int d = 0; d < DDIM; d++) p = __fmaf_rn(zr[d], crow[d], p);
            float dist = __fmaf_rn(-2.f, p, __fadd_rn(rr, g_snorm[k]));
            if (dist < bd || (dist == bd && k < bk)) { bd = dist; bk = k; }
        }
    } else {
#pragma unroll 1
        for (int gseg = 0; gseg < 4; gseg++) {
            int cnt = g_ccnt[n * 4 + gseg];
            const int* seg = g_cand + (n * 4 + gseg) * TCAND;
            for (int i = 0; i < cnt; i++) {
                int k = seg[i];
                const float* crow = cb + k * DDIM;
                float p = 0.f;
#pragma unroll
                for (int d = 0; d < DDIM; d++) p = __fmaf_rn(zr[d], crow[d], p);
                float dist = __fmaf_rn(-2.f, p, __fadd_rn(rr, g_snorm[k]));
                if (dist < bd || (dist == bd && k < bk)) { bd = dist; bk = k; }
            }
        }
    }
    g_idx[n] = bk;
}

// out[b, i, h, w] = codebook[idx[b, h, w], i]
__global__ void gather_kernel(const float* __restrict__ cb, float* __restrict__ out) {
    int o = blockIdx.x * blockDim.x + threadIdx.x;
    int hw = o & 4095;
    int i  = (o >> 12) & (DDIM - 1);
    int b  = o >> 19;
    int n  = (b << 12) | hw;
    out[o] = cb[g_idx[n] * DDIM + i];
}

extern "C" void kernel_launch(void* const* d_in, const int* in_sizes, int n_in,
                              void* d_out, int out_size) {
    const float* z  = (const float*)d_in[0];
    const float* cb = (const float*)d_in[1];
    float* out = (float*)d_out;

    cudaFuncSetAttribute(filter_kernel,
                         cudaFuncAttributeMaxDynamicSharedMemorySize, SMEM_TOTAL);

    cbprep_kernel<<<(KCODES + 255) / 256, 256>>>(cb);
    filter_kernel<<<NVEC / BM, NTHREADS, SMEM_TOTAL>>>(z);
    rescue_kernel<<<NVEC / 256, 256>>>(z, cb);
    gather_kernel<<<(NVEC * DDIM) / 256, 256>>>(cb, out);
}

// round 8
// speedup vs baseline: 1.0177x; 1.0177x over previous
#include <cuda_runtime.h>
#include <cstdint>

#define NVEC    131072
#define DDIM    128
#define KCODES  1024
#define BM      64               // vectors per CTA (filter)
#define CHUNK   256              // codes per chunk
#define NCHUNKS (KCODES / CHUNK)
#define NTHREADS 256
#define TCAND   2                // candidate slots per (vector, lane)

// filter smem word offsets
#define ZQ_STR  68
#define CS_STR  260
#define W_ZQ    0
#define W_CS    (32 * ZQ_STR)            // 2176  (fp32 z staging overlays this)
#define W_SS    (W_CS + 32 * CS_STR)     // 10496
#define W_TWOB  (W_SS + KCODES)          // 11520
#define W_NSC   (W_TWOB + 64)            // 11584
#define W_INV   (W_NSC + 64)             // 11648
#define W_TOTAL (W_INV + 64)             // 11712 words = 46848 B (static smem ok)

typedef unsigned long long u64;

__device__ int           g_cq[KCODES * 32];      // int8 codebook, packed words [k][dw]
__device__ float         g_snorm[KCODES];        // exact sequential ||c||^2
__device__ int           g_camax_bits = 0;       // max |c| (float bits, atomicMax)
__device__ int           g_cl1_bits   = 0;       // max L1(c) (float bits)
__device__ unsigned char g_ccnt[32][NVEC];       // candidate counts per (lane, vec)
__device__ int           g_cand[32][NVEC][TCAND];
__device__ int           g_idx[NVEC];

// ---- codebook stats: exact snorm + global amax / maxL1 (atomicMax idempotent) ----
__global__ void cbstat_kernel(const float* __restrict__ cb) {
    int k = blockIdx.x * blockDim.x + threadIdx.x;
    if (k >= KCODES) return;
    const float4* row = (const float4*)(cb + k * DDIM);
    float s = 0.f, amax = 0.f, l1 = 0.f;
#pragma unroll
    for (int i = 0; i < 32; i++) {
        float4 v = row[i];
        s = __fadd_rn(s, __fmul_rn(v.x, v.x));
        s = __fadd_rn(s, __fmul_rn(v.y, v.y));
        s = __fadd_rn(s, __fmul_rn(v.z, v.z));
        s = __fadd_rn(s, __fmul_rn(v.w, v.w));
        amax = fmaxf(amax, fmaxf(fmaxf(fabsf(v.x), fabsf(v.y)),
                                 fmaxf(fabsf(v.z), fabsf(v.w))));
        l1 += fabsf(v.x) + fabsf(v.y) + fabsf(v.z) + fabsf(v.w);
    }
    g_snorm[k] = s;
    atomicMax(&g_camax_bits, __float_as_int(amax));
    atomicMax(&g_cl1_bits, __float_as_int(l1));
}

__device__ __forceinline__ int pack4(float a, float b, float c, float d, float inv) {
    int x0 = __float2int_rn(a * inv) & 0xff;
    int x1 = __float2int_rn(b * inv) & 0xff;
    int x2 = __float2int_rn(c * inv) & 0xff;
    int x3 = __float2int_rn(d * inv) & 0xff;
    return x0 | (x1 << 8) | (x2 << 16) | (x3 << 24);
}

__global__ void cbquant_kernel(const float* __restrict__ cb) {
    int k = blockIdx.x * blockDim.x + threadIdx.x;
    if (k >= KCODES) return;
    float inv = 127.f / fmaxf(__int_as_float(g_camax_bits), 1e-30f);
    const float4* row = (const float4*)(cb + k * DDIM);
#pragma unroll
    for (int w = 0; w < 32; w++) {
        float4 v = row[w];
        g_cq[k * 32 + w] = pack4(v.x, v.y, v.z, v.w, inv);
    }
}

// ---- filter: int8 dp4a GEMM + margin capture (provable superset) ----
__global__ void __launch_bounds__(NTHREADS)
filter_kernel(const float* __restrict__ z) {
    __shared__ int smem[W_TOTAL];
    int*   zq   = smem + W_ZQ;
    int*   cs   = smem + W_CS;
    float* ss   = (float*)(smem + W_SS);
    float* twoB = (float*)(smem + W_TWOB);
    float* nsc  = (float*)(smem + W_NSC);
    float* invs = (float*)(smem + W_INV);

    const int tid = threadIdx.x, tn = tid >> 5, tk = tid & 31;
    const int nbase = blockIdx.x * BM;
    const float* zb = z + (size_t)(nbase >> 12) * (DDIM * 4096) + (nbase & 4095);

    for (int i = tid; i < KCODES; i += NTHREADS) ss[i] = g_snorm[i];

    // Stage z fp32 [d][v] into the CS region (dead until chunk loop).
    float* zs = (float*)cs;
    for (int e = tid; e < DDIM * 32; e += NTHREADS) {
        int d = e >> 5, v2 = e & 31;
        *(float2*)(zs + d * BM + v2 * 2) = *(const float2*)(zb + (size_t)d * 4096 + v2 * 2);
    }
    __syncthreads();

    // Per-vector stats -> scale + rigorous bound (any fp order; slack covers rounding).
    if (tid < BM) {
        float amax = 0.f, l1 = 0.f;
#pragma unroll 8
        for (int d = 0; d < DDIM; d++) {
            float v = zs[d * BM + tid];
            amax = fmaxf(amax, fabsf(v));
            l1 += fabsf(v);
        }
        float sz = fmaxf(amax, 1e-30f) / 127.f;
        float sc = fmaxf(__int_as_float(g_camax_bits), 1e-30f) / 127.f;
        float ml1c = __int_as_float(g_cl1_bits);
        float B = 0.5f * sc * (l1 + 64.f * sz)
                + 0.5f * sz * (ml1c + 64.f * sc)
                + 32.f * sz * sc;
        twoB[tid] = 2.f * B * 1.001f + 6e-5f;  // fp slack + fp32 quantized-tie window
        nsc[tid]  = -2.f * sz * sc;
        invs[tid] = 127.f / fmaxf(amax, 1e-30f);
    }
    __syncthreads();

    // Quantize z -> zq words [dw][v] (4 d's per word).
    for (int e = tid; e < 32 * BM; e += NTHREADS) {
        int dw = e >> 6, v = e & 63;
        float inv = invs[v];
        zq[dw * ZQ_STR + v] = pack4(zs[(4 * dw + 0) * BM + v], zs[(4 * dw + 1) * BM + v],
                                    zs[(4 * dw + 2) * BM + v], zs[(4 * dw + 3) * BM + v], inv);
    }

    float tB[8], tns[8], rm[8];
    int cnt[8], c0r[8], c1r[8];
#pragma unroll
    for (int i = 0; i < 8; i++) { rm[i] = 3.4e38f; cnt[i] = 0; c0r[i] = 0; c1r[i] = 0; }
    // twoB/nsc for this warp's 8 vectors (written above; __syncthreads below orders it)

    for (int ch = 0; ch < NCHUNKS; ch++) {
        __syncthreads();
        // Fill code chunk: cs[dw][k] from g_cq[k][dw] (gmem coalesced).
        const int* src = g_cq + (ch * CHUNK) * 32;
        for (int e = tid; e < CHUNK * 32; e += NTHREADS) {
            int k = e >> 5, dw = e & 31;
            cs[dw * CS_STR + k] = src[e];
        }
        __syncthreads();
        if (ch == 0) {
#pragma unroll
            for (int i = 0; i < 8; i++) { tB[i] = twoB[tn * 8 + i]; tns[i] = nsc[tn * 8 + i]; }
        }

        int acc[64];
#pragma unroll
        for (int a = 0; a < 64; a++) acc[a] = 0;

#pragma unroll 4
        for (int dw = 0; dw < 32; dw++) {
            const int* zp = zq + dw * ZQ_STR + tn * 8;
            const int* cp = cs + dw * CS_STR + tk * 8;
            int4 z0 = *(const int4*)zp, z1 = *(const int4*)(zp + 4);
            int4 d0 = *(const int4*)cp, d1 = *(const int4*)(cp + 4);
            int zr[8] = {z0.x, z0.y, z0.z, z0.w, z1.x, z1.y, z1.z, z1.w};
            int cr[8] = {d0.x, d0.y, d0.z, d0.w, d1.x, d1.y, d1.z, d1.w};
#pragma unroll
            for (int i = 0; i < 8; i++)
#pragma unroll
                for (int j = 0; j < 8; j++)
                    acc[i * 8 + j] = __dp4a(zr[i], cr[j], acc[i * 8 + j]);
        }

        // d_hat = s_k - 2*sz*sc*p (||z||^2 cancels in argmin). Overlay acc with bits.
        const int kb = ch * CHUNK + tk * 8;
        float sj[8];
#pragma unroll
        for (int j = 0; j < 8; j++) sj[j] = ss[kb + j];
        float cm[8];
#pragma unroll
        for (int i = 0; i < 8; i++) {
            float mn = 3.4e38f;
#pragma unroll
            for (int j = 0; j < 8; j++) {
                float d = __fmaf_rn(tns[i], (float)acc[i * 8 + j], sj[j]);
                acc[i * 8 + j] = __float_as_int(d);
                mn = fminf(mn, d);
            }
            cm[i] = mn;
        }
#pragma unroll
        for (int i = 0; i < 8; i++) {
#pragma unroll
            for (int off = 16; off > 0; off >>= 1)
                cm[i] = fminf(cm[i], __shfl_xor_sync(~0u, cm[i], off));
            rm[i] = fminf(rm[i], cm[i]);
        }
#pragma unroll
        for (int i = 0; i < 8; i++) {
            float t = rm[i] + tB[i];
#pragma unroll
            for (int j = 0; j < 8; j++) {
                if (__int_as_float(acc[i * 8 + j]) <= t) {
                    if (cnt[i] == 0) c0r[i] = kb + j;
                    else if (cnt[i] == 1) c1r[i] = kb + j;
                    cnt[i]++;
                }
            }
        }
    }

    const int n0 = nbase + tn * 8;
    u64 pk = 0;
#pragma unroll
    for (int i = 0; i < 8; i++) pk |= (u64)(cnt[i] > 3 ? 3 : cnt[i]) << (8 * i);
    *(u64*)&g_ccnt[tk][n0] = pk;
#pragma unroll
    for (int i = 0; i < 8; i++) {
        if (cnt[i] > 0) g_cand[tk][n0 + i][0] = c0r[i];
        if (cnt[i] > 1) g_cand[tk][n0 + i][1] = c1r[i];
    }
}

// ---- exact rescue: bit-identical reference arithmetic on candidates ----
__global__ void rescue_kernel(const float* __restrict__ z,
                              const float* __restrict__ cb) {
    int n = blockIdx.x * blockDim.x + threadIdx.x;
    int total = 0, lastlane = 0;
    bool full = false;
#pragma unroll
    for (int lane = 0; lane < 32; lane++) {
        int c = g_ccnt[lane][n];
        if (c > 2) full = true;
        if (c > 0) { total += c; lastlane = lane; }
    }
    if (!full && total == 1) { g_idx[n] = g_cand[lastlane][n][0]; return; }

    float zr[DDIM];
    const float* zp = z + (size_t)(n >> 12) * (DDIM * 4096) + (n & 4095);
#pragma unroll
    for (int d = 0; d < DDIM; d++) zr[d] = zp[(size_t)d * 4096];

    float rr = 0.f;
#pragma unroll
    for (int d = 0; d < DDIM; d++)
        rr = __fadd_rn(rr, __fmul_rn(zr[d], zr[d]));

    float bd = 3.4e38f;
    int bk = 0x7fffffff;
    if (full) {
        for (int k = 0; k < KCODES; k++) {
            const float* crow = cb + k * DDIM;
            float p = 0.f;
#pragma unroll
            for (int d = 0; d < DDIM; d++) p = __fmaf_rn(zr[d], crow[d], p);
            float dist = __fmaf_rn(-2.f, p, __fadd_rn(rr, g_snorm[k]));
            if (dist < bd || (dist == bd && k < bk)) { bd = dist; bk = k; }
        }
    } else {
#pragma unroll 1
        for (int lane = 0; lane < 32; lane++) {
            int c = g_ccnt[lane][n];
#pragma unroll 1
            for (int i = 0; i < c; i++) {
                int k = g_cand[lane][n][i];
                const float* crow = cb + k * DDIM;
                float p = 0.f;
#pragma unroll
                for (int d = 0; d < DDIM; d++) p = __fmaf_rn(zr[d], crow[d], p);
                float dist = __fmaf_rn(-2.f, p, __fadd_rn(rr, g_snorm[k]));
                if (dist < bd || (dist == bd && k < bk)) { bd = dist; bk = k; }
            }
        }
    }
    g_idx[n] = bk;
}

// ---- gather: float4 codebook reads, fully-coalesced writes ----
__global__ void gather_kernel(const float* __restrict__ cb, float* __restrict__ out) {
    int t = blockIdx.x * blockDim.x + threadIdx.x;   // t < NVEC*32
    int hw = t & 4095;
    int i4 = (t >> 12) & 31;
    int b  = t >> 17;
    int n  = (b << 12) | hw;
    float4 v = *(const float4*)(cb + g_idx[n] * DDIM + i4 * 4);
    size_t o = ((size_t)b << 19) | ((size_t)(i4 * 4) << 12) | (size_t)hw;
    out[o]         = v.x;
    out[o + 4096]  = v.y;
    out[o + 8192]  = v.z;
    out[o + 12288] = v.w;
}

extern "C" void kernel_launch(void* const* d_in, const int* in_sizes, int n_in,
                              void* d_out, int out_size) {
    const float* z  = (const float*)d_in[0];
    const float* cb = (const float*)d_in[1];
    float* out = (float*)d_out;

    cbstat_kernel<<<(KCODES + 255) / 256, 256>>>(cb);
    cbquant_kernel<<<(KCODES + 255) / 256, 256>>>(cb);
    filter_kernel<<<NVEC / BM, NTHREADS>>>(z);
    rescue_kernel<<<NVEC / 256, 256>>>(z, cb);
    gather_kernel<<<(NVEC * 32) / 256, 256>>>(cb, out);
}